// round 1
// baseline (speedup 1.0000x reference)
#include <cuda_runtime.h>
#include <math.h>

// ---------------- problem constants ----------------
#define D      64
#define S_SESS 16384
#define L_SESS 20
#define N_NODE (S_SESS * L_SESS)       // 327680
#define WEIGHT_DECAY 1e-5f

// ---------------- scratch (device globals; no cudaMalloc allowed) ----------
__device__ __align__(16) float g_C[2 * 64 * 192];     // G_i @ W_ih^T  [layer][d][j]
__device__ __align__(16) float g_Whh_t[64 * 192];     // W_hh^T        [d][j]
__device__ __align__(16) float g_W1t[64 * 64];        // W1^T [d][j]
__device__ __align__(16) float g_W2t[64 * 64];        // W2^T [d][j]
__device__ __align__(16) float g_W3t[128 * 64];       // W3^T [dd][o]
__device__ __align__(16) float g_hA[(size_t)N_NODE * 64];
__device__ __align__(16) float g_hB[(size_t)N_NODE * 64];
__device__ double g_accLoss;
__device__ double g_accReg;

// ---------------- prep: fold weights, transpose, zero accumulators ----------
__global__ void prep_kernel(const float* __restrict__ G,     // [2,64,64]
                            const float* __restrict__ Wih,   // [192,64]
                            const float* __restrict__ Whh,   // [192,64]
                            const float* __restrict__ W1,    // [64,64]
                            const float* __restrict__ W2,    // [64,64]
                            const float* __restrict__ W3)    // [64,128]
{
    int t = blockIdx.x * blockDim.x + threadIdx.x;
    if (t == 0) { g_accLoss = 0.0; g_accReg = 0.0; }
    if (t < 24576) {
        // C[i][d][j] = sum_k G[i][d][k] * Wih[j][k]
        int j = t % 192;
        int d = (t / 192) % 64;
        int i = t / 12288;
        const float* g = G + i * 4096 + d * 64;
        const float* w = Wih + j * 64;
        float a = 0.f;
        #pragma unroll 16
        for (int k = 0; k < 64; k++) a += g[k] * w[k];
        g_C[t] = a;
        return;
    }
    int u = t - 24576;
    if (u < 12288) { int j = u % 192, d = u / 192; g_Whh_t[u] = Whh[j * 64 + d]; return; }
    u -= 12288;
    if (u < 4096) { int j = u % 64, d = u / 64; g_W1t[u] = W1[j * 64 + d]; return; }
    u -= 4096;
    if (u < 4096) { int j = u % 64, d = u / 64; g_W2t[u] = W2[j * 64 + d]; return; }
    u -= 4096;
    if (u < 8192) { int o = u % 64, dd = u / 64; g_W3t[u] = W3[o * 128 + dd]; return; }
}

// ---------------- gather: h0 = item_emb[node_items - 1] ----------------
__global__ void gather_kernel(const float* __restrict__ item_emb,
                              const int* __restrict__ node_items)
{
    int t = blockIdx.x * blockDim.x + threadIdx.x;     // N*16 float4 slots
    if (t >= N_NODE * 16) return;
    int n = t >> 4;
    int v = t & 15;
    int it = node_items[n] - 1;
    reinterpret_cast<float4*>(g_hA)[t] =
        reinterpret_cast<const float4*>(item_emb)[(size_t)it * 16 + v];
}

// ---------------- fused GGC + GRU layer ----------------
// hout[n] = GRU(agg[n], hin[n]) where agg[n] = hin[n-1] @ C  (0 at session start)
// gi[j] = sum_d hprev[d]*C[d][j];  gh[j] = sum_d h[d]*Whh_t[d][j]
// Block: 80 nodes (4 sessions). Threads (32,16). Thread tile 5 rows x (2 j's).
#define GRU_SMEM_FLOATS (12288 + 12288 + 81 * 64 + 192 + 192)

__global__ void gru_kernel(int layer, int dir,
                           const float* __restrict__ bih,
                           const float* __restrict__ bhh)
{
    extern __shared__ float sm[];
    float* sC   = sm;                       // 12288
    float* sW   = sm + 12288;               // 12288
    float* sh   = sm + 24576;               // 81*64 (row 80 = zeros)
    float* sbih = sm + 24576 + 81 * 64;     // 192
    float* sbhh = sbih + 192;               // 192

    const float* hin  = dir ? g_hB : g_hA;
    float*       hout = dir ? g_hA : g_hB;
    const float* C = g_C + layer * 12288;

    int tx = threadIdx.x, ty = threadIdx.y;
    int tid = ty * 32 + tx;                 // 0..511
    int n0 = blockIdx.x * 80;

    {   // cooperative smem fills (float4)
        const float4* Cv = reinterpret_cast<const float4*>(C);
        float4* sCv = reinterpret_cast<float4*>(sC);
        for (int i = tid; i < 3072; i += 512) sCv[i] = Cv[i];
        const float4* Wv = reinterpret_cast<const float4*>(g_Whh_t);
        float4* sWv = reinterpret_cast<float4*>(sW);
        for (int i = tid; i < 3072; i += 512) sWv[i] = Wv[i];
        const float4* hv = reinterpret_cast<const float4*>(hin + (size_t)n0 * 64);
        float4* shv = reinterpret_cast<float4*>(sh);
        for (int i = tid; i < 1280; i += 512) shv[i] = hv[i];
        if (tid < 64) sh[80 * 64 + tid] = 0.f;
        if (tid < 192) { sbih[tid] = bih[tid]; sbhh[tid] = bhh[tid]; }
    }
    __syncthreads();

    int rows[5], prevs[5];
    #pragma unroll
    for (int m = 0; m < 5; m++) {
        rows[m] = ty + 16 * m;
        prevs[m] = (rows[m] % 20 == 0) ? 80 : rows[m] - 1;
    }

    // accS[m][c]: c=0,1 -> r-gate (j=tx, tx+32) gi+gh; c=2,3 -> z-gate gi+gh
    // accIn/accHn: n-gate gi and gh kept separate (j=tx, tx+32)
    float accS[5][4];
    float accIn[5][2], accHn[5][2];
    #pragma unroll
    for (int m = 0; m < 5; m++) {
        #pragma unroll
        for (int c = 0; c < 4; c++) accS[m][c] = 0.f;
        accIn[m][0] = accIn[m][1] = 0.f;
        accHn[m][0] = accHn[m][1] = 0.f;
    }

    #pragma unroll 4
    for (int k = 0; k < 64; k++) {
        float bc[6], bw[6];
        #pragma unroll
        for (int c = 0; c < 6; c++) {
            bc[c] = sC[k * 192 + tx + 32 * c];
            bw[c] = sW[k * 192 + tx + 32 * c];
        }
        #pragma unroll
        for (int m = 0; m < 5; m++) {
            float agi = sh[prevs[m] * 64 + k];
            float agh = sh[rows[m] * 64 + k];
            #pragma unroll
            for (int c = 0; c < 4; c++)
                accS[m][c] += agi * bc[c] + agh * bw[c];
            accIn[m][0] += agi * bc[4];
            accIn[m][1] += agi * bc[5];
            accHn[m][0] += agh * bw[4];
            accHn[m][1] += agh * bw[5];
        }
    }

    #pragma unroll
    for (int m = 0; m < 5; m++) {
        #pragma unroll
        for (int t = 0; t < 2; t++) {
            int j = tx + 32 * t;
            float r = 1.f / (1.f + expf(-(accS[m][t]     + sbih[j]      + sbhh[j])));
            float z = 1.f / (1.f + expf(-(accS[m][2 + t] + sbih[64 + j] + sbhh[64 + j])));
            float nn = tanhf(accIn[m][t] + sbih[128 + j] + r * (accHn[m][t] + sbhh[128 + j]));
            float hold = sh[rows[m] * 64 + j];
            hout[(size_t)(n0 + rows[m]) * 64 + j] = (1.f - z) * nn + z * hold;
        }
    }
}

// ---------------- fused relu + attention + readout + BPR loss ----------------
// One block = 8 sessions (160 nodes), 256 threads.
#define ATTN_SMEM_FLOATS (4096 + 4096 + 8192 + 10240 + 512 + 512 + 512 + 160 + 64 + 64 + 64 + 64 + 16)

__global__ void attn_kernel(const float* __restrict__ item_emb,
                            const float* __restrict__ b1,
                            const float* __restrict__ b2,
                            const float* __restrict__ b3,
                            const float* __restrict__ qw,
                            const float* __restrict__ qb,
                            const int* __restrict__ pos,
                            const int* __restrict__ neg)
{
    extern __shared__ float sm[];
    float* sW1t = sm;                 // 4096
    float* sW2t = sW1t + 4096;        // 4096
    float* sW3t = sW2t + 4096;        // 8192
    float* sh   = sW3t + 8192;        // 8*20*64 = 10240 (relu'd)
    float* p1   = sh + 10240;         // 512
    float* sg   = p1 + 512;           // 512
    float* shh  = sg + 512;           // 512
    float* alph = shh + 512;          // 160
    float* sqw  = alph + 160;         // 64
    float* sb1  = sqw + 64;           // 64
    float* sb2  = sb1 + 64;           // 64
    float* sb3  = sb2 + 64;           // 64
    float* lossp = sb3 + 64;          // 8
    float* regp  = lossp + 8;         // 8

    int tid = threadIdx.x;            // 256
    int lane = tid & 31, wid = tid >> 5;
    int s0 = blockIdx.x * 8;

    {
        const float4* a = reinterpret_cast<const float4*>(g_W1t);
        float4* b = reinterpret_cast<float4*>(sW1t);
        for (int i = tid; i < 1024; i += 256) b[i] = a[i];
        a = reinterpret_cast<const float4*>(g_W2t);
        b = reinterpret_cast<float4*>(sW2t);
        for (int i = tid; i < 1024; i += 256) b[i] = a[i];
        a = reinterpret_cast<const float4*>(g_W3t);
        b = reinterpret_cast<float4*>(sW3t);
        for (int i = tid; i < 2048; i += 256) b[i] = a[i];
        if (tid < 64) { sqw[tid] = qw[tid]; sb1[tid] = b1[tid]; sb2[tid] = b2[tid]; sb3[tid] = b3[tid]; }
        // relu'd h tile: 160 nodes
        const float4* hv = reinterpret_cast<const float4*>(g_hA + (size_t)s0 * 20 * 64);
        float4* shv = reinterpret_cast<float4*>(sh);
        for (int i = tid; i < 2560; i += 256) {
            float4 v = hv[i];
            v.x = fmaxf(v.x, 0.f); v.y = fmaxf(v.y, 0.f);
            v.z = fmaxf(v.z, 0.f); v.w = fmaxf(v.w, 0.f);
            shv[i] = v;
        }
    }
    __syncthreads();

    // p1[s][j] = b1[j] + v_n[s] . W1t[:,j]
    for (int o = tid; o < 512; o += 256) {
        int s = o >> 6, j = o & 63;
        const float* vn = sh + (s * 20 + 19) * 64;
        float a = sb1[j];
        #pragma unroll 16
        for (int d = 0; d < 64; d++) a += vn[d] * sW1t[d * 64 + j];
        p1[o] = a;
    }
    __syncthreads();

    // alpha per node (warp-per-node)
    for (int nn = wid; nn < 160; nn += 8) {
        int s = nn / 20;
        const float* hr = sh + nn * 64;
        float part = 0.f;
        #pragma unroll
        for (int t = 0; t < 2; t++) {
            int j = lane + 32 * t;
            float a = p1[s * 64 + j] + sb2[j];
            #pragma unroll 16
            for (int d = 0; d < 64; d++) a += hr[d] * sW2t[d * 64 + j];
            part += sqw[j] / (1.f + expf(-a));
        }
        #pragma unroll
        for (int off = 16; off > 0; off >>= 1)
            part += __shfl_xor_sync(0xffffffffu, part, off);
        if (lane == 0) alph[nn] = part + qb[0];
    }
    __syncthreads();

    // s_g[s][d] = sum_l alpha * h
    for (int o = tid; o < 512; o += 256) {
        int s = o >> 6, d = o & 63;
        float a = 0.f;
        #pragma unroll
        for (int l = 0; l < 20; l++) a += alph[s * 20 + l] * sh[(s * 20 + l) * 64 + d];
        sg[o] = a;
    }
    __syncthreads();

    // s_h[s][o] = b3 + [v_n, s_g] @ W3^T
    for (int o = tid; o < 512; o += 256) {
        int s = o >> 6, oo = o & 63;
        const float* vn = sh + (s * 20 + 19) * 64;
        const float* sgp = sg + s * 64;
        float a = sb3[oo];
        #pragma unroll 16
        for (int d = 0; d < 64; d++) a += vn[d] * sW3t[d * 64 + oo];
        #pragma unroll 16
        for (int d = 0; d < 64; d++) a += sgp[d] * sW3t[(64 + d) * 64 + oo];
        shh[o] = a;
    }
    __syncthreads();

    // BPR loss + reg, warp per session
    {
        int s = wid;  // 8 warps, 8 sessions
        int ps = pos[s0 + s], ns = neg[s0 + s];
        float pp = 0.f, np_ = 0.f, r2 = 0.f;
        #pragma unroll
        for (int t = 0; t < 2; t++) {
            int d = lane + 32 * t;
            float sv = shh[s * 64 + d];
            float pe = item_emb[(size_t)ps * 64 + d];
            float ne = item_emb[(size_t)ns * 64 + d];
            pp += sv * pe;
            np_ += sv * ne;
            r2 += sv * sv + pe * pe + ne * ne;
        }
        #pragma unroll
        for (int off = 16; off > 0; off >>= 1) {
            pp  += __shfl_xor_sync(0xffffffffu, pp, off);
            np_ += __shfl_xor_sync(0xffffffffu, np_, off);
            r2  += __shfl_xor_sync(0xffffffffu, r2, off);
        }
        if (lane == 0) {
            float x = pp - np_;
            // -log_sigmoid(x) = softplus(-x), stable
            float ls = fmaxf(-x, 0.f) + log1pf(expf(-fabsf(x)));
            lossp[wid] = ls;
            regp[wid] = r2;
        }
    }
    __syncthreads();
    if (tid == 0) {
        float tl = 0.f, tr = 0.f;
        #pragma unroll
        for (int w = 0; w < 8; w++) { tl += lossp[w]; tr += regp[w]; }
        atomicAdd(&g_accLoss, (double)tl);
        atomicAdd(&g_accReg, (double)tr);
    }
}

__global__ void finalize_kernel(float* out)
{
    float loss = (float)g_accLoss;
    float reg = (float)(WEIGHT_DECAY * g_accReg);
    out[0] = loss + reg;
    out[1] = loss;
    out[2] = reg;
    out[3] = reg;
    out[4] = reg;
}

// ---------------- launch ----------------
extern "C" void kernel_launch(void* const* d_in, const int* in_sizes, int n_in,
                              void* d_out, int out_size)
{
    const float* item_emb = (const float*)d_in[0];
    const float* ggc      = (const float*)d_in[1];
    const float* W_ih     = (const float*)d_in[2];
    const float* b_ih     = (const float*)d_in[3];
    const float* W_hh     = (const float*)d_in[4];
    const float* b_hh     = (const float*)d_in[5];
    const float* W1       = (const float*)d_in[6];
    const float* b1       = (const float*)d_in[7];
    const float* W2       = (const float*)d_in[8];
    const float* b2       = (const float*)d_in[9];
    const float* q_w      = (const float*)d_in[10];
    const float* q_b      = (const float*)d_in[11];
    const float* W3       = (const float*)d_in[12];
    const float* b3       = (const float*)d_in[13];
    const int* node_items = (const int*)d_in[14];
    // d_in[15] edge_index, d_in[16] batch: structure is deterministic (chain), unused
    const int* pos        = (const int*)d_in[17];
    const int* neg        = (const int*)d_in[18];
    float* out = (float*)d_out;

    cudaFuncSetAttribute(gru_kernel, cudaFuncAttributeMaxDynamicSharedMemorySize,
                         GRU_SMEM_FLOATS * (int)sizeof(float));
    cudaFuncSetAttribute(attn_kernel, cudaFuncAttributeMaxDynamicSharedMemorySize,
                         ATTN_SMEM_FLOATS * (int)sizeof(float));

    prep_kernel<<<208, 256>>>(ggc, W_ih, W_hh, W1, W2, W3);
    gather_kernel<<<(N_NODE * 16) / 256, 256>>>(item_emb, node_items);
    gru_kernel<<<N_NODE / 80, dim3(32, 16), GRU_SMEM_FLOATS * sizeof(float)>>>(0, 0, b_ih, b_hh); // A->B
    gru_kernel<<<N_NODE / 80, dim3(32, 16), GRU_SMEM_FLOATS * sizeof(float)>>>(1, 1, b_ih, b_hh); // B->A
    attn_kernel<<<S_SESS / 8, 256, ATTN_SMEM_FLOATS * sizeof(float)>>>(
        item_emb, b1, b2, b3, q_w, q_b, pos, neg);
    finalize_kernel<<<1, 1>>>(out);
}